// round 1
// baseline (speedup 1.0000x reference)
#include <cuda_runtime.h>
#include <cstdint>

// Problem constants (fixed by the dataset)
static const int NN = 50000;   // nodes
static const int NE = 800000;  // edges
static const int FD = 128;     // input features
static const int HD = 256;     // hidden
static const int NG = 128;     // graphs
static const int NC = 10;      // classes

// Scratch (device globals — no allocation allowed)
__device__ float g_h[(long long)NN * HD];     // GEMM output / message source
__device__ float g_z[(long long)NN * HD];     // propagation output (pre-activation)
__device__ float g_inv[NN];                   // 1/sqrt(deg)
__device__ int   g_deg[NN];
__device__ float g_gmsum[NG * HD];
__device__ int   g_cnt[NG];
__device__ float g_gm[NG * HD];

// ---------------- degree / norm ----------------
__global__ void k_zero_deg() {
    int i = blockIdx.x * blockDim.x + threadIdx.x;
    if (i < NN) g_deg[i] = 0;
}
__global__ void k_count(const int* __restrict__ dst) {
    int e = blockIdx.x * blockDim.x + threadIdx.x;
    if (e < NE) atomicAdd(&g_deg[dst[e]], 1);
}
__global__ void k_inv() {
    int i = blockIdx.x * blockDim.x + threadIdx.x;
    if (i < NN) g_inv[i] = rsqrtf((float)(g_deg[i] + 1));  // +1 self loop
}

// ---------------- GEMM: g_h = A @ B ----------------
// MODE 0: A = Aext (x), KD = FD
// MODE 1: A = g_z + graph_hidden[batch[row]]          (first hidden layer)
// MODE 2: A = relu(g_z) + graph_hidden[batch[row]]    (later layers)
template<int KD, int MODE>
__global__ __launch_bounds__(256, 2)
void k_gemm(const float* __restrict__ Aext, const float* __restrict__ B,
            const int* __restrict__ batch, const float* __restrict__ gh) {
    __shared__ float As[8][128];
    __shared__ float Bs[8][128];
    const int tid = threadIdx.x;
    const int tx = tid & 15;
    const int ty = tid >> 4;
    const int rowBase = blockIdx.x * 128;
    const int colBase = blockIdx.y * 128;

    const int ar   = tid >> 1;            // 0..127 (A tile row)
    const int aRow = rowBase + ar;
    const int aK   = (tid & 1) * 4;       // 0 or 4
    const int bRow = tid >> 5;            // 0..7
    const int bc   = (tid & 31) * 4;      // 0..124

    float acc[8][8];
#pragma unroll
    for (int i = 0; i < 8; i++)
#pragma unroll
        for (int j = 0; j < 8; j++) acc[i][j] = 0.f;

    int bi = 0;
    if (MODE != 0 && aRow < NN) bi = batch[aRow];

    for (int kt = 0; kt < KD; kt += 8) {
        float4 av = make_float4(0.f, 0.f, 0.f, 0.f);
        if (aRow < NN) {
            if (MODE == 0) {
                av = *(const float4*)(Aext + (long long)aRow * KD + kt + aK);
            } else {
                float4 z = *(const float4*)(g_z + (long long)aRow * HD + kt + aK);
                float4 r = *(const float4*)(gh + (long long)bi * HD + kt + aK);
                if (MODE == 2) {
                    z.x = fmaxf(z.x, 0.f); z.y = fmaxf(z.y, 0.f);
                    z.z = fmaxf(z.z, 0.f); z.w = fmaxf(z.w, 0.f);
                }
                av.x = z.x + r.x; av.y = z.y + r.y;
                av.z = z.z + r.z; av.w = z.w + r.w;
            }
        }
        As[aK + 0][ar] = av.x; As[aK + 1][ar] = av.y;
        As[aK + 2][ar] = av.z; As[aK + 3][ar] = av.w;

        float4 bv = *(const float4*)(B + (long long)(kt + bRow) * HD + colBase + bc);
        *(float4*)&Bs[bRow][bc] = bv;
        __syncthreads();
#pragma unroll
        for (int kk = 0; kk < 8; kk++) {
            float a[8], b[8];
            *(float4*)(a)     = *(const float4*)&As[kk][ty * 8];
            *(float4*)(a + 4) = *(const float4*)&As[kk][ty * 8 + 4];
            *(float4*)(b)     = *(const float4*)&Bs[kk][tx * 8];
            *(float4*)(b + 4) = *(const float4*)&Bs[kk][tx * 8 + 4];
#pragma unroll
            for (int i = 0; i < 8; i++)
#pragma unroll
                for (int j = 0; j < 8; j++)
                    acc[i][j] = fmaf(a[i], b[j], acc[i][j]);
        }
        __syncthreads();
    }
#pragma unroll
    for (int i = 0; i < 8; i++) {
        int r = rowBase + ty * 8 + i;
        if (r < NN) {
            float4 v0 = make_float4(acc[i][0], acc[i][1], acc[i][2], acc[i][3]);
            float4 v1 = make_float4(acc[i][4], acc[i][5], acc[i][6], acc[i][7]);
            *(float4*)(g_h + (long long)r * HD + colBase + tx * 8)     = v0;
            *(float4*)(g_h + (long long)r * HD + colBase + tx * 8 + 4) = v1;
        }
    }
}

// ---------------- propagation ----------------
// init: g_z[i] = bias + g_h[i] * (1/deg_i)   (self-loop contribution, norm = inv^2)
__global__ void k_prop_init(const float* __restrict__ bias) {
    long long t = (long long)blockIdx.x * blockDim.x + threadIdx.x;
    if (t >= (long long)NN * 64) return;
    int i = (int)(t >> 6);
    int c = (int)(t & 63);
    float iv = g_inv[i];
    float inv2 = iv * iv;
    float4 h4 = *(const float4*)(g_h + (long long)i * HD + c * 4);
    float4 b4 = *(const float4*)(bias + c * 4);
    float4 z;
    z.x = fmaf(h4.x, inv2, b4.x);
    z.y = fmaf(h4.y, inv2, b4.y);
    z.z = fmaf(h4.z, inv2, b4.z);
    z.w = fmaf(h4.w, inv2, b4.w);
    *(float4*)(g_z + (long long)i * HD + c * 4) = z;
}

// edges: warp per edge; g_z[dst] += g_h[src] * inv[src]*inv[dst] via vector red
__global__ void k_prop_edges(const int* __restrict__ src, const int* __restrict__ dst) {
    int w = (blockIdx.x * blockDim.x + threadIdx.x) >> 5;
    int lane = threadIdx.x & 31;
    if (w >= NE) return;
    int s = src[w];
    int d = dst[w];
    float wt = g_inv[s] * g_inv[d];
    const float4* hs = (const float4*)(g_h + (long long)s * HD);
    float* od = g_z + (long long)d * HD;
#pragma unroll
    for (int c = lane; c < 64; c += 32) {
        float4 v = hs[c];
        v.x *= wt; v.y *= wt; v.z *= wt; v.w *= wt;
        asm volatile("red.global.add.v4.f32 [%0], {%1,%2,%3,%4};"
                     :: "l"(od + c * 4), "f"(v.x), "f"(v.y), "f"(v.z), "f"(v.w)
                     : "memory");
    }
}

// ---------------- pooling + head ----------------
__global__ void k_pool_zero() {
    int i = blockIdx.x * blockDim.x + threadIdx.x;
    if (i < NG * HD) g_gmsum[i] = 0.f;
    if (i < NG) g_cnt[i] = 0;
}
__global__ void k_pool_cnt(const int* __restrict__ batch) {
    int i = blockIdx.x * blockDim.x + threadIdx.x;
    if (i < NN) atomicAdd(&g_cnt[batch[i]], 1);
}
__global__ void k_pool_accum(const int* __restrict__ batch) {
    int w = (blockIdx.x * blockDim.x + threadIdx.x) >> 5;
    int lane = threadIdx.x & 31;
    if (w >= NN) return;
    int b = batch[w];
    const float4* z4 = (const float4*)(g_z + (long long)w * HD);
    float* gs = g_gmsum + b * HD;
#pragma unroll
    for (int c = lane; c < 64; c += 32) {
        float4 v = z4[c];
        v.x = fmaxf(v.x, 0.f); v.y = fmaxf(v.y, 0.f);
        v.z = fmaxf(v.z, 0.f); v.w = fmaxf(v.w, 0.f);
        asm volatile("red.global.add.v4.f32 [%0], {%1,%2,%3,%4};"
                     :: "l"(gs + c * 4), "f"(v.x), "f"(v.y), "f"(v.z), "f"(v.w)
                     : "memory");
    }
}
__global__ void k_pool_final(const float* __restrict__ gh, float* __restrict__ out) {
    int t = blockIdx.x * blockDim.x + threadIdx.x;
    if (t >= NG * HD) return;
    int g = t / HD;
    float cnt = (float)max(g_cnt[g], 1);
    float v = g_gmsum[t] / cnt + gh[t];
    g_gm[t] = v;
    out[NG * NC + t] = v;   // gm goes after y in the flattened output
}
__global__ void k_y(const float* __restrict__ Wlin, const float* __restrict__ blin,
                    float* __restrict__ out) {
    int t = blockIdx.x * blockDim.x + threadIdx.x;
    if (t >= NG * NC) return;
    int g = t / NC, c = t % NC;
    float s = blin[c];
    const float* gm = g_gm + g * HD;
#pragma unroll 8
    for (int k = 0; k < HD; k++) s = fmaf(gm[k], Wlin[k * NC + c], s);
    out[t] = s;
}

// ---------------- launch ----------------
extern "C" void kernel_launch(void* const* d_in, const int* in_sizes, int n_in,
                              void* d_out, int out_size) {
    const float* x     = (const float*)d_in[0];
    const int*   ei    = (const int*)d_in[1];
    const int*   src   = ei;           // edge_index[0]
    const int*   dst   = ei + NE;      // edge_index[1]
    const int*   batch = (const int*)d_in[2];
    const float* gh    = (const float*)d_in[3];
    const float* W0    = (const float*)d_in[4];
    const float* b0    = (const float*)d_in[5];
    const float* Ws    = (const float*)d_in[6];
    const float* bs    = (const float*)d_in[7];
    const float* Wlin  = (const float*)d_in[8];
    const float* blin  = (const float*)d_in[9];
    float* out = (float*)d_out;

    // degrees + norm
    k_zero_deg<<<(NN + 255) / 256, 256>>>();
    k_count<<<(NE + 255) / 256, 256>>>(dst);
    k_inv<<<(NN + 255) / 256, 256>>>();

    dim3 ggrid((NN + 127) / 128, HD / 128);
    const int initBlocks = (int)(((long long)NN * 64 + 255) / 256);
    const int edgeBlocks = (int)(((long long)NE * 32 + 255) / 256);

    // layer 0: h = x @ W0 ; propagate (+ self loop + bias)
    k_gemm<FD, 0><<<ggrid, 256>>>(x, W0, nullptr, nullptr);
    k_prop_init<<<initBlocks, 256>>>(b0);
    k_prop_edges<<<edgeBlocks, 256>>>(src, dst);

    // 3 hidden layers: A = act(z) + res ; h = A @ Ws[l] ; propagate
    for (int l = 0; l < 3; l++) {
        const float* B = Ws + (long long)l * HD * HD;
        if (l == 0) k_gemm<HD, 1><<<ggrid, 256>>>(nullptr, B, batch, gh);
        else        k_gemm<HD, 2><<<ggrid, 256>>>(nullptr, B, batch, gh);
        k_prop_init<<<initBlocks, 256>>>(bs + l * HD);
        k_prop_edges<<<edgeBlocks, 256>>>(src, dst);
    }

    // pooling (with final relu) + residual + linear head
    k_pool_zero<<<(NG * HD + 255) / 256, 256>>>();
    k_pool_cnt<<<(NN + 255) / 256, 256>>>(batch);
    k_pool_accum<<<(int)(((long long)NN * 32 + 255) / 256), 256>>>(batch);
    k_pool_final<<<(NG * HD + 255) / 256, 256>>>(gh, out);
    k_y<<<(NG * NC + 255) / 256, 256>>>(Wlin, blin, out);
}

// round 2
// speedup vs baseline: 1.0864x; 1.0864x over previous
#include <cuda_runtime.h>
#include <cstdint>

// Problem constants
static const int NN = 50000;
static const int NE = 800000;
static const int FD = 128;
static const int HD = 256;
static const int NG = 128;
static const int NC = 10;

// Scratch
__device__ float g_h[(long long)NN * HD];
__device__ float g_z[(long long)NN * HD];
__device__ float g_inv[NN];
__device__ int   g_deg[NN];
__device__ float g_gmsum[NG * HD];
__device__ int   g_cnt[NG];
__device__ float g_gm[NG * HD];

// ---------------- degree / norm ----------------
__global__ void k_zero_deg() {
    int i = blockIdx.x * blockDim.x + threadIdx.x;
    if (i < NN) g_deg[i] = 0;
}
__global__ void k_count(const int* __restrict__ dst) {
    int e = blockIdx.x * blockDim.x + threadIdx.x;
    if (e < NE) atomicAdd(&g_deg[dst[e]], 1);
}
__global__ void k_inv() {
    int i = blockIdx.x * blockDim.x + threadIdx.x;
    if (i < NN) g_inv[i] = rsqrtf((float)(g_deg[i] + 1));
}

// ---------------- TF32 helpers ----------------
__device__ __forceinline__ unsigned f2tf(float f) {
    unsigned u;
    asm("cvt.rna.tf32.f32 %0, %1;" : "=r"(u) : "f"(f));
    return u;
}
__device__ __forceinline__ void split_tf32(float f, unsigned& hi, unsigned& lo) {
    hi = f2tf(f);
    lo = f2tf(f - __uint_as_float(hi));
}
__device__ __forceinline__ void mma_tf32(float4& c, const unsigned a[4], const unsigned b[2]) {
    asm volatile(
        "mma.sync.aligned.m16n8k8.row.col.f32.tf32.tf32.f32 "
        "{%0,%1,%2,%3}, {%4,%5,%6,%7}, {%8,%9}, {%0,%1,%2,%3};"
        : "+f"(c.x), "+f"(c.y), "+f"(c.z), "+f"(c.w)
        : "r"(a[0]), "r"(a[1]), "r"(a[2]), "r"(a[3]), "r"(b[0]), "r"(b[1]));
}

// ---------------- tensor-core GEMM: g_h = A @ B ----------------
// MODE 0: A = Aext (x)
// MODE 1: A = g_z + gh[batch[row]]
// MODE 2: A = relu(g_z) + gh[batch[row]]
// Split-TF32 (3 mma terms) => ~fp32 accuracy.
#define AS_STRIDE 36
#define BS_STRIDE 136
template<int KD, int MODE>
__global__ __launch_bounds__(256, 2)
void k_gemm(const float* __restrict__ Aext, const float* __restrict__ B,
            const int* __restrict__ batch, const float* __restrict__ gh) {
    __shared__ float As[128 * AS_STRIDE];
    __shared__ float Bs[32 * BS_STRIDE];
    const int tid  = threadIdx.x;
    const int lane = tid & 31;
    const int warp = tid >> 5;
    const int wm = warp >> 1;   // 0..3  (M warp)
    const int wn = warp & 1;    // 0..1  (N warp)
    const int rowBase = blockIdx.x * 128;
    const int colBase = blockIdx.y * 128;

    // global->smem mapping
    const int arow   = tid >> 1;        // 0..127
    const int aRowG  = rowBase + arow;
    const int akBase = (tid & 1) * 16;
    const int brow   = tid >> 3;        // 0..31
    const int bcol   = (tid & 7) * 16;

    float4 acc[2][8];
#pragma unroll
    for (int i = 0; i < 2; i++)
#pragma unroll
        for (int j = 0; j < 8; j++) acc[i][j] = make_float4(0.f, 0.f, 0.f, 0.f);

    const bool rowOK = (aRowG < NN);
    const float* aPtr;
    const float* ghRow = nullptr;
    if (MODE == 0) {
        aPtr = Aext + (size_t)aRowG * KD;
    } else {
        int bi = 0;
        if (rowOK) bi = batch[aRowG];
        aPtr  = g_z + (size_t)aRowG * HD;
        ghRow = gh + (size_t)bi * HD;
    }

    for (int kt = 0; kt < KD; kt += 32) {
        // ---- stage A tile (with fused epilogue of previous layer) ----
#pragma unroll
        for (int q = 0; q < 4; q++) {
            int k = akBase + q * 4;
            float4 v = make_float4(0.f, 0.f, 0.f, 0.f);
            if (rowOK) {
                if (MODE == 0) {
                    v = *(const float4*)(aPtr + kt + k);
                } else {
                    float4 z = *(const float4*)(aPtr + kt + k);
                    float4 r = *(const float4*)(ghRow + kt + k);
                    if (MODE == 2) {
                        z.x = fmaxf(z.x, 0.f); z.y = fmaxf(z.y, 0.f);
                        z.z = fmaxf(z.z, 0.f); z.w = fmaxf(z.w, 0.f);
                    }
                    v.x = z.x + r.x; v.y = z.y + r.y;
                    v.z = z.z + r.z; v.w = z.w + r.w;
                }
            }
            *(float4*)(As + arow * AS_STRIDE + k) = v;
        }
        // ---- stage B tile ----
#pragma unroll
        for (int q = 0; q < 4; q++) {
            int c = bcol + q * 4;
            float4 v = *(const float4*)(B + (size_t)(kt + brow) * HD + colBase + c);
            *(float4*)(Bs + brow * BS_STRIDE + c) = v;
        }
        __syncthreads();

#pragma unroll
        for (int k8 = 0; k8 < 4; k8++) {
            const int kk = k8 * 8 + (lane & 3);
            // A fragments (2 m16 tiles), split hi/lo
            unsigned ah[2][4], al[2][4];
#pragma unroll
            for (int i = 0; i < 2; i++) {
                int r = wm * 32 + i * 16 + (lane >> 2);
                float v0 = As[r * AS_STRIDE + kk];
                float v1 = As[(r + 8) * AS_STRIDE + kk];
                float v2 = As[r * AS_STRIDE + kk + 4];
                float v3 = As[(r + 8) * AS_STRIDE + kk + 4];
                split_tf32(v0, ah[i][0], al[i][0]);
                split_tf32(v1, ah[i][1], al[i][1]);
                split_tf32(v2, ah[i][2], al[i][2]);
                split_tf32(v3, ah[i][3], al[i][3]);
            }
            // B in two halves to cap register pressure
#pragma unroll
            for (int h = 0; h < 2; h++) {
                unsigned bh[4][2], bl[4][2];
#pragma unroll
                for (int j = 0; j < 4; j++) {
                    int c = wn * 64 + h * 32 + j * 8 + (lane >> 2);
                    float v0 = Bs[kk * BS_STRIDE + c];
                    float v1 = Bs[(kk + 4) * BS_STRIDE + c];
                    split_tf32(v0, bh[j][0], bl[j][0]);
                    split_tf32(v1, bh[j][1], bl[j][1]);
                }
#pragma unroll
                for (int i = 0; i < 2; i++)
#pragma unroll
                    for (int j = 0; j < 4; j++) {
                        float4& c4 = acc[i][h * 4 + j];
                        mma_tf32(c4, ah[i], bh[j]);   // hi*hi
                        mma_tf32(c4, ah[i], bl[j]);   // hi*lo
                        mma_tf32(c4, al[i], bh[j]);   // lo*hi
                    }
            }
        }
        __syncthreads();
    }

    // ---- store C ----
#pragma unroll
    for (int i = 0; i < 2; i++) {
        int r0 = rowBase + wm * 32 + i * 16 + (lane >> 2);
#pragma unroll
        for (int j = 0; j < 8; j++) {
            int c = colBase + wn * 64 + j * 8 + 2 * (lane & 3);
            float4 v = acc[i][j];
            if (r0 < NN)
                *(float2*)(g_h + (size_t)r0 * HD + c) = make_float2(v.x, v.y);
            if (r0 + 8 < NN)
                *(float2*)(g_h + (size_t)(r0 + 8) * HD + c) = make_float2(v.z, v.w);
        }
    }
}

// ---------------- propagation ----------------
__global__ void k_prop_init(const float* __restrict__ bias) {
    long long t = (long long)blockIdx.x * blockDim.x + threadIdx.x;
    if (t >= (long long)NN * 64) return;
    int i = (int)(t >> 6);
    int c = (int)(t & 63);
    float iv = g_inv[i];
    float inv2 = iv * iv;
    float4 h4 = *(const float4*)(g_h + (long long)i * HD + c * 4);
    float4 b4 = *(const float4*)(bias + c * 4);
    float4 z;
    z.x = fmaf(h4.x, inv2, b4.x);
    z.y = fmaf(h4.y, inv2, b4.y);
    z.z = fmaf(h4.z, inv2, b4.z);
    z.w = fmaf(h4.w, inv2, b4.w);
    *(float4*)(g_z + (long long)i * HD + c * 4) = z;
}

__global__ void k_prop_edges(const int* __restrict__ src, const int* __restrict__ dst) {
    int w = (blockIdx.x * blockDim.x + threadIdx.x) >> 5;
    int lane = threadIdx.x & 31;
    if (w >= NE) return;
    int s = src[w];
    int d = dst[w];
    float wt = g_inv[s] * g_inv[d];
    const float4* hs = (const float4*)(g_h + (long long)s * HD);
    float* od = g_z + (long long)d * HD;
#pragma unroll
    for (int c = lane; c < 64; c += 32) {
        float4 v = hs[c];
        v.x *= wt; v.y *= wt; v.z *= wt; v.w *= wt;
        asm volatile("red.global.add.v4.f32 [%0], {%1,%2,%3,%4};"
                     :: "l"(od + c * 4), "f"(v.x), "f"(v.y), "f"(v.z), "f"(v.w)
                     : "memory");
    }
}

// ---------------- pooling + head ----------------
__global__ void k_pool_zero() {
    int i = blockIdx.x * blockDim.x + threadIdx.x;
    if (i < NG * HD) g_gmsum[i] = 0.f;
    if (i < NG) g_cnt[i] = 0;
}
__global__ void k_pool_cnt(const int* __restrict__ batch) {
    int i = blockIdx.x * blockDim.x + threadIdx.x;
    if (i < NN) atomicAdd(&g_cnt[batch[i]], 1);
}
__global__ void k_pool_accum(const int* __restrict__ batch) {
    int w = (blockIdx.x * blockDim.x + threadIdx.x) >> 5;
    int lane = threadIdx.x & 31;
    if (w >= NN) return;
    int b = batch[w];
    const float4* z4 = (const float4*)(g_z + (long long)w * HD);
    float* gs = g_gmsum + b * HD;
#pragma unroll
    for (int c = lane; c < 64; c += 32) {
        float4 v = z4[c];
        v.x = fmaxf(v.x, 0.f); v.y = fmaxf(v.y, 0.f);
        v.z = fmaxf(v.z, 0.f); v.w = fmaxf(v.w, 0.f);
        asm volatile("red.global.add.v4.f32 [%0], {%1,%2,%3,%4};"
                     :: "l"(gs + c * 4), "f"(v.x), "f"(v.y), "f"(v.z), "f"(v.w)
                     : "memory");
    }
}
__global__ void k_pool_final(const float* __restrict__ gh, float* __restrict__ out) {
    int t = blockIdx.x * blockDim.x + threadIdx.x;
    if (t >= NG * HD) return;
    int g = t / HD;
    float cnt = (float)max(g_cnt[g], 1);
    float v = g_gmsum[t] / cnt + gh[t];
    g_gm[t] = v;
    out[NG * NC + t] = v;
}
__global__ void k_y(const float* __restrict__ Wlin, const float* __restrict__ blin,
                    float* __restrict__ out) {
    int t = blockIdx.x * blockDim.x + threadIdx.x;
    if (t >= NG * NC) return;
    int g = t / NC, c = t % NC;
    float s = blin[c];
    const float* gm = g_gm + g * HD;
#pragma unroll 8
    for (int k = 0; k < HD; k++) s = fmaf(gm[k], Wlin[k * NC + c], s);
    out[t] = s;
}

// ---------------- launch ----------------
extern "C" void kernel_launch(void* const* d_in, const int* in_sizes, int n_in,
                              void* d_out, int out_size) {
    const float* x     = (const float*)d_in[0];
    const int*   ei    = (const int*)d_in[1];
    const int*   src   = ei;
    const int*   dst   = ei + NE;
    const int*   batch = (const int*)d_in[2];
    const float* gh    = (const float*)d_in[3];
    const float* W0    = (const float*)d_in[4];
    const float* b0    = (const float*)d_in[5];
    const float* Ws    = (const float*)d_in[6];
    const float* bs    = (const float*)d_in[7];
    const float* Wlin  = (const float*)d_in[8];
    const float* blin  = (const float*)d_in[9];
    float* out = (float*)d_out;

    k_zero_deg<<<(NN + 255) / 256, 256>>>();
    k_count<<<(NE + 255) / 256, 256>>>(dst);
    k_inv<<<(NN + 255) / 256, 256>>>();

    dim3 ggrid((NN + 127) / 128, HD / 128);
    const int initBlocks = (int)(((long long)NN * 64 + 255) / 256);
    const int edgeBlocks = (int)(((long long)NE * 32 + 255) / 256);

    k_gemm<FD, 0><<<ggrid, 256>>>(x, W0, nullptr, nullptr);
    k_prop_init<<<initBlocks, 256>>>(b0);
    k_prop_edges<<<edgeBlocks, 256>>>(src, dst);

    for (int l = 0; l < 3; l++) {
        const float* B = Ws + (long long)l * HD * HD;
        if (l == 0) k_gemm<HD, 1><<<ggrid, 256>>>(nullptr, B, batch, gh);
        else        k_gemm<HD, 2><<<ggrid, 256>>>(nullptr, B, batch, gh);
        k_prop_init<<<initBlocks, 256>>>(bs + l * HD);
        k_prop_edges<<<edgeBlocks, 256>>>(src, dst);
    }

    k_pool_zero<<<(NG * HD + 255) / 256, 256>>>();
    k_pool_cnt<<<(NN + 255) / 256, 256>>>(batch);
    k_pool_accum<<<(int)(((long long)NN * 32 + 255) / 256), 256>>>(batch);
    k_pool_final<<<(NG * HD + 255) / 256, 256>>>(gh, out);
    k_y<<<(NG * NC + 255) / 256, 256>>>(Wlin, blin, out);
}

// round 3
// speedup vs baseline: 1.2150x; 1.1184x over previous
#include <cuda_runtime.h>
#include <cstdint>

static const int NN = 50000;
static const int NE = 800000;
static const int FD = 128;
static const int HD = 256;
static const int NG = 128;
static const int NC = 10;

// Scratch
__device__ float g_h[(long long)NN * HD];
__device__ float g_z[(long long)NN * HD];
__device__ float g_inv[NN];
__device__ int   g_deg[NN];
__device__ int   g_rowptr[NN + 1];
__device__ int   g_pos[NN];
__device__ int   g_csrc[NE];
__device__ int   g_bsum[256];
__device__ int   g_boff[256];
__device__ float g_gmsum[NG * HD];
__device__ int   g_cnt[NG];
__device__ float g_gm[NG * HD];

// ---------------- degree / norm ----------------
__global__ void k_zero_deg() {
    int i = blockIdx.x * blockDim.x + threadIdx.x;
    if (i < NN) g_deg[i] = 0;
}
__global__ void k_count(const int* __restrict__ dst) {
    int e = blockIdx.x * blockDim.x + threadIdx.x;
    if (e < NE) atomicAdd(&g_deg[dst[e]], 1);
}
__global__ void k_inv() {
    int i = blockIdx.x * blockDim.x + threadIdx.x;
    if (i < NN) g_inv[i] = rsqrtf((float)(g_deg[i] + 1));
}

// ---------------- CSR build: scan + scatter ----------------
#define SCAN_B 256
__global__ void k_scan1() {   // per-block sums of deg
    __shared__ int sh[SCAN_B];
    int i = blockIdx.x * SCAN_B + threadIdx.x;
    int v = (i < NN) ? g_deg[i] : 0;
    sh[threadIdx.x] = v;
    __syncthreads();
    for (int s = SCAN_B / 2; s > 0; s >>= 1) {
        if (threadIdx.x < s) sh[threadIdx.x] += sh[threadIdx.x + s];
        __syncthreads();
    }
    if (threadIdx.x == 0) g_bsum[blockIdx.x] = sh[0];
}
__global__ void k_scan2(int nblocks) {  // serial scan of partials
    if (threadIdx.x == 0) {
        int acc = 0;
        for (int b = 0; b < nblocks; b++) { g_boff[b] = acc; acc += g_bsum[b]; }
        g_rowptr[NN] = acc;
    }
}
__global__ void k_scan3() {   // per-block exclusive scan + offset
    __shared__ int sh[SCAN_B];
    int i = blockIdx.x * SCAN_B + threadIdx.x;
    int v = (i < NN) ? g_deg[i] : 0;
    sh[threadIdx.x] = v;
    __syncthreads();
    // Hillis-Steele inclusive
    for (int s = 1; s < SCAN_B; s <<= 1) {
        int t = (threadIdx.x >= s) ? sh[threadIdx.x - s] : 0;
        __syncthreads();
        sh[threadIdx.x] += t;
        __syncthreads();
    }
    if (i < NN) {
        int excl = g_boff[blockIdx.x] + sh[threadIdx.x] - v;
        g_rowptr[i] = excl;
        g_pos[i] = excl;
    }
}
__global__ void k_scatter(const int* __restrict__ src, const int* __restrict__ dst) {
    int e = blockIdx.x * blockDim.x + threadIdx.x;
    if (e >= NE) return;
    int d = dst[e];
    int slot = atomicAdd(&g_pos[d], 1);
    g_csrc[slot] = src[e];
}

// ---------------- TF32 helpers ----------------
__device__ __forceinline__ unsigned f2tf(float f) {
    unsigned u;
    asm("cvt.rna.tf32.f32 %0, %1;" : "=r"(u) : "f"(f));
    return u;
}
__device__ __forceinline__ void split_tf32(float f, unsigned& hi, unsigned& lo) {
    hi = f2tf(f);
    lo = f2tf(f - __uint_as_float(hi));
}
__device__ __forceinline__ void mma_tf32(float4& c, const unsigned a[4], const unsigned b[2]) {
    asm volatile(
        "mma.sync.aligned.m16n8k8.row.col.f32.tf32.tf32.f32 "
        "{%0,%1,%2,%3}, {%4,%5,%6,%7}, {%8,%9}, {%0,%1,%2,%3};"
        : "+f"(c.x), "+f"(c.y), "+f"(c.z), "+f"(c.w)
        : "r"(a[0]), "r"(a[1]), "r"(a[2]), "r"(a[3]), "r"(b[0]), "r"(b[1]));
}

// ---------------- tensor GEMM with smem-staged hi/lo ----------------
// MODE 0: A = Aext ; MODE 1: A = g_z + gh[batch] ; MODE 2: A = relu(g_z) + gh[batch]
#define KSTEP 16
#define AS_W 40    // u32 stride per A row  (16*2 + 8 pad;  40 % 32 == 8)
#define BS_W 264   // u32 stride per B k-row (128*2 + 8 pad; 264 % 32 == 8)
template<int KD, int MODE>
__global__ __launch_bounds__(256)
void k_gemm(const float* __restrict__ Aext, const float* __restrict__ B,
            const int* __restrict__ batch, const float* __restrict__ gh) {
    __shared__ unsigned As[128 * AS_W];
    __shared__ unsigned Bs[KSTEP * BS_W];
    const int tid  = threadIdx.x;
    const int lane = tid & 31;
    const int warp = tid >> 5;
    const int wm = warp >> 1;
    const int wn = warp & 1;
    const int rowBase = blockIdx.x * 128;
    const int colBase = blockIdx.y * 128;

    // staging maps
    const int arow = tid >> 1;            // 0..127
    const int akb  = (tid & 1) * 8;       // 0 or 8
    const int bk   = tid & 15;            // 0..15
    const int bcb  = (tid >> 4) * 8;      // 0..120

    const int aRowG = rowBase + arow;
    const bool rowOK = (aRowG < NN);

    const float* aPtr;
    const float* ghRow = nullptr;
    if (MODE == 0) {
        aPtr = Aext + (size_t)aRowG * KD;
    } else {
        int bi = 0;
        if (rowOK) bi = batch[aRowG];
        aPtr  = g_z + (size_t)aRowG * HD;
        ghRow = gh + (size_t)bi * HD;
    }
    const float* bPtr = B + (size_t)bk * HD + colBase + bcb;

    float4 acc[2][8];
#pragma unroll
    for (int i = 0; i < 2; i++)
#pragma unroll
        for (int j = 0; j < 8; j++) acc[i][j] = make_float4(0.f, 0.f, 0.f, 0.f);

    float4 aR0, aR1, bR0, bR1;

    // ---- register load of tile kt ----
#define LOAD_REGS(kt)                                                          \
    {                                                                          \
        aR0 = make_float4(0.f, 0.f, 0.f, 0.f);                                 \
        aR1 = aR0;                                                             \
        if (rowOK) {                                                           \
            if (MODE == 0) {                                                   \
                aR0 = *(const float4*)(aPtr + (kt) + akb);                     \
                aR1 = *(const float4*)(aPtr + (kt) + akb + 4);                 \
            } else {                                                           \
                float4 z0 = *(const float4*)(aPtr + (kt) + akb);               \
                float4 z1 = *(const float4*)(aPtr + (kt) + akb + 4);           \
                float4 r0 = *(const float4*)(ghRow + (kt) + akb);              \
                float4 r1 = *(const float4*)(ghRow + (kt) + akb + 4);          \
                if (MODE == 2) {                                               \
                    z0.x = fmaxf(z0.x, 0.f); z0.y = fmaxf(z0.y, 0.f);          \
                    z0.z = fmaxf(z0.z, 0.f); z0.w = fmaxf(z0.w, 0.f);          \
                    z1.x = fmaxf(z1.x, 0.f); z1.y = fmaxf(z1.y, 0.f);          \
                    z1.z = fmaxf(z1.z, 0.f); z1.w = fmaxf(z1.w, 0.f);          \
                }                                                              \
                aR0 = make_float4(z0.x + r0.x, z0.y + r0.y, z0.z + r0.z, z0.w + r0.w); \
                aR1 = make_float4(z1.x + r1.x, z1.y + r1.y, z1.z + r1.z, z1.w + r1.w); \
            }                                                                  \
        }                                                                      \
        bR0 = *(const float4*)(bPtr + (size_t)(kt) * HD);                      \
        bR1 = *(const float4*)(bPtr + (size_t)(kt) * HD + 4);                  \
    }

    LOAD_REGS(0);

    for (int kt = 0; kt < KD; kt += KSTEP) {
        // ---- stage converted hi/lo into smem ----
        {
            float av[8] = {aR0.x, aR0.y, aR0.z, aR0.w, aR1.x, aR1.y, aR1.z, aR1.w};
            float bv[8] = {bR0.x, bR0.y, bR0.z, bR0.w, bR1.x, bR1.y, bR1.z, bR1.w};
#pragma unroll
            for (int p = 0; p < 4; p++) {
                unsigned h0, l0, h1, l1;
                split_tf32(av[2 * p], h0, l0);
                split_tf32(av[2 * p + 1], h1, l1);
                *(uint4*)&As[arow * AS_W + (akb + 2 * p) * 2] = make_uint4(h0, l0, h1, l1);
                split_tf32(bv[2 * p], h0, l0);
                split_tf32(bv[2 * p + 1], h1, l1);
                *(uint4*)&Bs[bk * BS_W + (bcb + 2 * p) * 2] = make_uint4(h0, l0, h1, l1);
            }
        }
        __syncthreads();
        if (kt + KSTEP < KD) { LOAD_REGS(kt + KSTEP); }

        // ---- compute ----
#pragma unroll
        for (int k8 = 0; k8 < 2; k8++) {
            const int kk = k8 * 8 + (lane & 3);
            unsigned ah[2][4], al[2][4];
#pragma unroll
            for (int i = 0; i < 2; i++) {
                int r = wm * 32 + i * 16 + (lane >> 2);
                uint2 p;
                p = *(const uint2*)&As[r * AS_W + kk * 2];           ah[i][0] = p.x; al[i][0] = p.y;
                p = *(const uint2*)&As[(r + 8) * AS_W + kk * 2];     ah[i][1] = p.x; al[i][1] = p.y;
                p = *(const uint2*)&As[r * AS_W + (kk + 4) * 2];     ah[i][2] = p.x; al[i][2] = p.y;
                p = *(const uint2*)&As[(r + 8) * AS_W + (kk + 4) * 2]; ah[i][3] = p.x; al[i][3] = p.y;
            }
#pragma unroll
            for (int hh = 0; hh < 2; hh++) {
                unsigned bh[4][2], bl[4][2];
#pragma unroll
                for (int j = 0; j < 4; j++) {
                    int c = wn * 64 + hh * 32 + j * 8 + (lane >> 2);
                    uint2 p;
                    p = *(const uint2*)&Bs[kk * BS_W + c * 2];       bh[j][0] = p.x; bl[j][0] = p.y;
                    p = *(const uint2*)&Bs[(kk + 4) * BS_W + c * 2]; bh[j][1] = p.x; bl[j][1] = p.y;
                }
#pragma unroll
                for (int i = 0; i < 2; i++)
#pragma unroll
                    for (int j = 0; j < 4; j++) {
                        float4& c4 = acc[i][hh * 4 + j];
                        mma_tf32(c4, ah[i], bh[j]);
                        mma_tf32(c4, ah[i], bl[j]);
                        mma_tf32(c4, al[i], bh[j]);
                    }
            }
        }
        __syncthreads();
    }

    // ---- store ----
#pragma unroll
    for (int i = 0; i < 2; i++) {
        int r0 = rowBase + wm * 32 + i * 16 + (lane >> 2);
#pragma unroll
        for (int j = 0; j < 8; j++) {
            int c = colBase + wn * 64 + j * 8 + 2 * (lane & 3);
            float4 v = acc[i][j];
            if (r0 < NN)
                *(float2*)(g_h + (size_t)r0 * HD + c) = make_float2(v.x, v.y);
            if (r0 + 8 < NN)
                *(float2*)(g_h + (size_t)(r0 + 8) * HD + c) = make_float2(v.z, v.w);
        }
    }
#undef LOAD_REGS
}

// ---------------- CSR gather propagation (self loop + bias fused) ----------------
__global__ __launch_bounds__(256)
void k_prop_csr(const float* __restrict__ bias) {
    int node = blockIdx.x * 8 + (threadIdx.x >> 5);
    int lane = threadIdx.x & 31;
    if (node >= NN) return;
    float invd = g_inv[node];
    int start = g_rowptr[node];
    int end   = g_rowptr[node + 1];
    const float* hrow = g_h + (size_t)node * HD;
    float s2 = invd * invd;
    float4 h0 = *(const float4*)(hrow + lane * 4);
    float4 h1 = *(const float4*)(hrow + 128 + lane * 4);
    float4 b0 = *(const float4*)(bias + lane * 4);
    float4 b1 = *(const float4*)(bias + 128 + lane * 4);
    float4 acc0 = make_float4(fmaf(h0.x, s2, b0.x), fmaf(h0.y, s2, b0.y),
                              fmaf(h0.z, s2, b0.z), fmaf(h0.w, s2, b0.w));
    float4 acc1 = make_float4(fmaf(h1.x, s2, b1.x), fmaf(h1.y, s2, b1.y),
                              fmaf(h1.z, s2, b1.z), fmaf(h1.w, s2, b1.w));
    int e = start;
    for (; e + 1 < end; e += 2) {
        int s0 = g_csrc[e];
        int s1 = g_csrc[e + 1];
        float w0 = g_inv[s0] * invd;
        float w1 = g_inv[s1] * invd;
        const float* p0 = g_h + (size_t)s0 * HD;
        const float* p1 = g_h + (size_t)s1 * HD;
        float4 u00 = *(const float4*)(p0 + lane * 4);
        float4 u01 = *(const float4*)(p0 + 128 + lane * 4);
        float4 u10 = *(const float4*)(p1 + lane * 4);
        float4 u11 = *(const float4*)(p1 + 128 + lane * 4);
        acc0.x = fmaf(u00.x, w0, acc0.x); acc0.y = fmaf(u00.y, w0, acc0.y);
        acc0.z = fmaf(u00.z, w0, acc0.z); acc0.w = fmaf(u00.w, w0, acc0.w);
        acc1.x = fmaf(u01.x, w0, acc1.x); acc1.y = fmaf(u01.y, w0, acc1.y);
        acc1.z = fmaf(u01.z, w0, acc1.z); acc1.w = fmaf(u01.w, w0, acc1.w);
        acc0.x = fmaf(u10.x, w1, acc0.x); acc0.y = fmaf(u10.y, w1, acc0.y);
        acc0.z = fmaf(u10.z, w1, acc0.z); acc0.w = fmaf(u10.w, w1, acc0.w);
        acc1.x = fmaf(u11.x, w1, acc1.x); acc1.y = fmaf(u11.y, w1, acc1.y);
        acc1.z = fmaf(u11.z, w1, acc1.z); acc1.w = fmaf(u11.w, w1, acc1.w);
    }
    if (e < end) {
        int s0 = g_csrc[e];
        float w0 = g_inv[s0] * invd;
        const float* p0 = g_h + (size_t)s0 * HD;
        float4 u00 = *(const float4*)(p0 + lane * 4);
        float4 u01 = *(const float4*)(p0 + 128 + lane * 4);
        acc0.x = fmaf(u00.x, w0, acc0.x); acc0.y = fmaf(u00.y, w0, acc0.y);
        acc0.z = fmaf(u00.z, w0, acc0.z); acc0.w = fmaf(u00.w, w0, acc0.w);
        acc1.x = fmaf(u01.x, w0, acc1.x); acc1.y = fmaf(u01.y, w0, acc1.y);
        acc1.z = fmaf(u01.z, w0, acc1.z); acc1.w = fmaf(u01.w, w0, acc1.w);
    }
    float* zrow = g_z + (size_t)node * HD;
    *(float4*)(zrow + lane * 4) = acc0;
    *(float4*)(zrow + 128 + lane * 4) = acc1;
}

// ---------------- pooling + head ----------------
__global__ void k_pool_zero() {
    int i = blockIdx.x * blockDim.x + threadIdx.x;
    if (i < NG * HD) g_gmsum[i] = 0.f;
    if (i < NG) g_cnt[i] = 0;
}
__global__ void k_pool_cnt(const int* __restrict__ batch) {
    int i = blockIdx.x * blockDim.x + threadIdx.x;
    if (i < NN) atomicAdd(&g_cnt[batch[i]], 1);
}
__global__ void k_pool_accum(const int* __restrict__ batch) {
    int w = (blockIdx.x * blockDim.x + threadIdx.x) >> 5;
    int lane = threadIdx.x & 31;
    if (w >= NN) return;
    int b = batch[w];
    const float4* z4 = (const float4*)(g_z + (long long)w * HD);
    float* gs = g_gmsum + b * HD;
#pragma unroll
    for (int c = lane; c < 64; c += 32) {
        float4 v = z4[c];
        v.x = fmaxf(v.x, 0.f); v.y = fmaxf(v.y, 0.f);
        v.z = fmaxf(v.z, 0.f); v.w = fmaxf(v.w, 0.f);
        asm volatile("red.global.add.v4.f32 [%0], {%1,%2,%3,%4};"
                     :: "l"(gs + c * 4), "f"(v.x), "f"(v.y), "f"(v.z), "f"(v.w)
                     : "memory");
    }
}
__global__ void k_pool_final(const float* __restrict__ gh, float* __restrict__ out) {
    int t = blockIdx.x * blockDim.x + threadIdx.x;
    if (t >= NG * HD) return;
    int g = t / HD;
    float cnt = (float)max(g_cnt[g], 1);
    float v = g_gmsum[t] / cnt + gh[t];
    g_gm[t] = v;
    out[NG * NC + t] = v;
}
__global__ void k_y(const float* __restrict__ Wlin, const float* __restrict__ blin,
                    float* __restrict__ out) {
    int t = blockIdx.x * blockDim.x + threadIdx.x;
    if (t >= NG * NC) return;
    int g = t / NC, c = t % NC;
    float s = blin[c];
    const float* gm = g_gm + g * HD;
#pragma unroll 8
    for (int k = 0; k < HD; k++) s = fmaf(gm[k], Wlin[k * NC + c], s);
    out[t] = s;
}

// ---------------- launch ----------------
extern "C" void kernel_launch(void* const* d_in, const int* in_sizes, int n_in,
                              void* d_out, int out_size) {
    const float* x     = (const float*)d_in[0];
    const int*   ei    = (const int*)d_in[1];
    const int*   src   = ei;
    const int*   dst   = ei + NE;
    const int*   batch = (const int*)d_in[2];
    const float* gh    = (const float*)d_in[3];
    const float* W0    = (const float*)d_in[4];
    const float* b0    = (const float*)d_in[5];
    const float* Ws    = (const float*)d_in[6];
    const float* bs    = (const float*)d_in[7];
    const float* Wlin  = (const float*)d_in[8];
    const float* blin  = (const float*)d_in[9];
    float* out = (float*)d_out;

    // degrees + norm + CSR
    k_zero_deg<<<(NN + 255) / 256, 256>>>();
    k_count<<<(NE + 255) / 256, 256>>>(dst);
    k_inv<<<(NN + 255) / 256, 256>>>();
    const int nsb = (NN + SCAN_B - 1) / SCAN_B;   // 196
    k_scan1<<<nsb, SCAN_B>>>();
    k_scan2<<<1, 32>>>(nsb);
    k_scan3<<<nsb, SCAN_B>>>();
    k_scatter<<<(NE + 255) / 256, 256>>>(src, dst);

    dim3 ggrid((NN + 127) / 128, HD / 128);
    const int propBlocks = (NN + 7) / 8;

    k_gemm<FD, 0><<<ggrid, 256>>>(x, W0, nullptr, nullptr);
    k_prop_csr<<<propBlocks, 256>>>(b0);

    for (int l = 0; l < 3; l++) {
        const float* B = Ws + (long long)l * HD * HD;
        if (l == 0) k_gemm<HD, 1><<<ggrid, 256>>>(nullptr, B, batch, gh);
        else        k_gemm<HD, 2><<<ggrid, 256>>>(nullptr, B, batch, gh);
        k_prop_csr<<<propBlocks, 256>>>(bs + l * HD);
    }

    k_pool_zero<<<(NG * HD + 255) / 256, 256>>>();
    k_pool_cnt<<<(NN + 255) / 256, 256>>>(batch);
    k_pool_accum<<<(int)(((long long)NN * 32 + 255) / 256), 256>>>(batch);
    k_pool_final<<<(NG * HD + 255) / 256, 256>>>(gh, out);
    k_y<<<(NG * NC + 255) / 256, 256>>>(Wlin, blin, out);
}

// round 4
// speedup vs baseline: 1.3165x; 1.0835x over previous
#include <cuda_runtime.h>
#include <cstdint>

static const int NN = 50000;
static const int NE = 800000;
static const int FD = 128;
static const int HD = 256;
static const int NG = 128;
static const int NC = 10;
static const int NL = 3;

// Scratch
__device__ float g_h[(long long)NN * HD];
__device__ float g_z[(long long)NN * HD];
__device__ float g_inv[NN];
__device__ int   g_deg[NN];
__device__ int   g_rowptr[NN + 1];
__device__ int   g_pos[NN];
__device__ int   g_csrc[NE];
__device__ int   g_bsum[256];
__device__ int   g_boff[256];
__device__ float g_R[NL * NG * HD];
__device__ float g_gmsum[NG * HD];
__device__ int   g_cnt[NG];
__device__ float g_gm[NG * HD];

// ---------------- init ----------------
__global__ void k_init() {
    int i = blockIdx.x * blockDim.x + threadIdx.x;
    if (i < NN) g_deg[i] = 0;
    if (i < NG * HD) g_gmsum[i] = 0.f;
    if (i < NG) g_cnt[i] = 0;
}
__global__ void k_count(const int* __restrict__ dst, const int* __restrict__ batch) {
    int e = blockIdx.x * blockDim.x + threadIdx.x;
    if (e < NE) atomicAdd(&g_deg[dst[e]], 1);
    if (e < NN) atomicAdd(&g_cnt[batch[e]], 1);
}

// ---------------- CSR build ----------------
#define SCAN_B 256
__global__ void k_scan1() {
    __shared__ int sh[SCAN_B];
    int i = blockIdx.x * SCAN_B + threadIdx.x;
    int v = (i < NN) ? g_deg[i] : 0;
    sh[threadIdx.x] = v;
    __syncthreads();
    for (int s = SCAN_B / 2; s > 0; s >>= 1) {
        if (threadIdx.x < s) sh[threadIdx.x] += sh[threadIdx.x + s];
        __syncthreads();
    }
    if (threadIdx.x == 0) g_bsum[blockIdx.x] = sh[0];
}
__global__ void k_scan2(int nblocks) {
    if (threadIdx.x == 0) {
        int acc = 0;
        for (int b = 0; b < nblocks; b++) { g_boff[b] = acc; acc += g_bsum[b]; }
        g_rowptr[NN] = acc;
    }
}
__global__ void k_scan3() {
    __shared__ int sh[SCAN_B];
    int i = blockIdx.x * SCAN_B + threadIdx.x;
    int v = (i < NN) ? g_deg[i] : 0;
    sh[threadIdx.x] = v;
    __syncthreads();
    for (int s = 1; s < SCAN_B; s <<= 1) {
        int t = (threadIdx.x >= s) ? sh[threadIdx.x - s] : 0;
        __syncthreads();
        sh[threadIdx.x] += t;
        __syncthreads();
    }
    if (i < NN) {
        int excl = g_boff[blockIdx.x] + sh[threadIdx.x] - v;
        g_rowptr[i] = excl;
        g_pos[i] = excl;
        g_inv[i] = rsqrtf((float)(v + 1));
    }
}
__global__ void k_scatter(const int* __restrict__ src, const int* __restrict__ dst) {
    int e = blockIdx.x * blockDim.x + threadIdx.x;
    if (e >= NE) return;
    int d = dst[e];
    int slot = atomicAdd(&g_pos[d], 1);
    g_csrc[slot] = src[e];
}

// ---------------- small GEMM: g_R[l] = gh @ Ws[l] ----------------
__global__ __launch_bounds__(256)
void k_rgemm(const float* __restrict__ gh, const float* __restrict__ Ws) {
    __shared__ float Ag[128 * 36];
    __shared__ float Bg[32 * 132];
    const float* B = Ws + (size_t)blockIdx.y * HD * HD;
    const int colBase = blockIdx.x * 128;
    const int tid = threadIdx.x;
    const int tx = tid & 15, ty = tid >> 4;
    float acc[8][8];
#pragma unroll
    for (int i = 0; i < 8; i++)
#pragma unroll
        for (int j = 0; j < 8; j++) acc[i][j] = 0.f;

    const int ar = tid >> 1, ak = (tid & 1) * 16;
    const int br = tid >> 3, bc = (tid & 7) * 16;
    for (int kt = 0; kt < HD; kt += 32) {
#pragma unroll
        for (int q = 0; q < 4; q++) {
            float4 v = *(const float4*)(gh + (size_t)ar * HD + kt + ak + 4 * q);
            *(float4*)&Ag[ar * 36 + ak + 4 * q] = v;
            float4 w = *(const float4*)(B + (size_t)(kt + br) * HD + colBase + bc + 4 * q);
            *(float4*)&Bg[br * 132 + bc + 4 * q] = w;
        }
        __syncthreads();
#pragma unroll
        for (int kk = 0; kk < 32; kk++) {
            float a[8], b[8];
#pragma unroll
            for (int i = 0; i < 8; i++) a[i] = Ag[(ty * 8 + i) * 36 + kk];
            *(float4*)(b)     = *(const float4*)&Bg[kk * 132 + tx * 8];
            *(float4*)(b + 4) = *(const float4*)&Bg[kk * 132 + tx * 8 + 4];
#pragma unroll
            for (int i = 0; i < 8; i++)
#pragma unroll
                for (int j = 0; j < 8; j++) acc[i][j] = fmaf(a[i], b[j], acc[i][j]);
        }
        __syncthreads();
    }
    float* outp = g_R + (size_t)blockIdx.y * NG * HD;
#pragma unroll
    for (int i = 0; i < 8; i++)
#pragma unroll
        for (int j = 0; j < 2; j++)
            *(float4*)(outp + (size_t)(ty * 8 + i) * HD + colBase + tx * 8 + 4 * j) =
                make_float4(acc[i][4 * j], acc[i][4 * j + 1], acc[i][4 * j + 2], acc[i][4 * j + 3]);
}

// ---------------- TF32 helpers ----------------
__device__ __forceinline__ unsigned f2tf(float f) {
    unsigned u;
    asm("cvt.rna.tf32.f32 %0, %1;" : "=r"(u) : "f"(f));
    return u;
}
__device__ __forceinline__ void split_tf32(float f, unsigned& hi, unsigned& lo) {
    hi = f2tf(f);
    lo = f2tf(f - __uint_as_float(hi));
}
__device__ __forceinline__ void mma_tf32(float4& c, const unsigned a[4], const unsigned b[2]) {
    asm volatile(
        "mma.sync.aligned.m16n8k8.row.col.f32.tf32.tf32.f32 "
        "{%0,%1,%2,%3}, {%4,%5,%6,%7}, {%8,%9}, {%0,%1,%2,%3};"
        : "+f"(c.x), "+f"(c.y), "+f"(c.z), "+f"(c.w)
        : "r"(a[0]), "r"(a[1]), "r"(a[2]), "r"(a[3]), "r"(b[0]), "r"(b[1]));
}

// ---------------- main tensor GEMM ----------------
// LIDX < 0: A = Aext (x), no epilogue add.  LIDX >= 0: A = g_z, += g_R[LIDX][batch[row]].
#define KSTEP 16
#define AS_W 40
#define BS_W 264
template<int KD, int LIDX>
__global__ __launch_bounds__(256)
void k_gemm(const float* __restrict__ Aext, const float* __restrict__ B,
            const int* __restrict__ batch) {
    __shared__ unsigned As[128 * AS_W];
    __shared__ unsigned Bs[KSTEP * BS_W];
    const int tid  = threadIdx.x;
    const int lane = tid & 31;
    const int warp = tid >> 5;
    const int wm = warp >> 1;
    const int wn = warp & 1;
    const int rowBase = blockIdx.x * 128;
    const int colBase = blockIdx.y * 128;

    const int arow = tid >> 1;
    const int akb  = (tid & 1) * 8;
    const int bk   = tid & 15;
    const int bcb  = (tid >> 4) * 8;

    const int aRowG = rowBase + arow;
    const bool rowOK = (aRowG < NN);
    const float* aPtr = (LIDX < 0 ? Aext : (const float*)g_z) + (size_t)aRowG * KD;
    const float* bPtr = B + (size_t)bk * HD + colBase + bcb;

    float4 acc[2][8];
#pragma unroll
    for (int i = 0; i < 2; i++)
#pragma unroll
        for (int j = 0; j < 8; j++) acc[i][j] = make_float4(0.f, 0.f, 0.f, 0.f);

    float4 aR0, aR1, bR0, bR1;
#define LOAD_REGS(kt)                                              \
    {                                                              \
        aR0 = make_float4(0.f, 0.f, 0.f, 0.f); aR1 = aR0;          \
        if (rowOK) {                                               \
            aR0 = *(const float4*)(aPtr + (kt) + akb);             \
            aR1 = *(const float4*)(aPtr + (kt) + akb + 4);         \
        }                                                          \
        bR0 = *(const float4*)(bPtr + (size_t)(kt) * HD);          \
        bR1 = *(const float4*)(bPtr + (size_t)(kt) * HD + 4);      \
    }

    LOAD_REGS(0);
    for (int kt = 0; kt < KD; kt += KSTEP) {
        {
            float av[8] = {aR0.x, aR0.y, aR0.z, aR0.w, aR1.x, aR1.y, aR1.z, aR1.w};
            float bv[8] = {bR0.x, bR0.y, bR0.z, bR0.w, bR1.x, bR1.y, bR1.z, bR1.w};
#pragma unroll
            for (int p = 0; p < 4; p++) {
                unsigned h0, l0, h1, l1;
                split_tf32(av[2 * p], h0, l0);
                split_tf32(av[2 * p + 1], h1, l1);
                *(uint4*)&As[arow * AS_W + (akb + 2 * p) * 2] = make_uint4(h0, l0, h1, l1);
                split_tf32(bv[2 * p], h0, l0);
                split_tf32(bv[2 * p + 1], h1, l1);
                *(uint4*)&Bs[bk * BS_W + (bcb + 2 * p) * 2] = make_uint4(h0, l0, h1, l1);
            }
        }
        __syncthreads();
        if (kt + KSTEP < KD) { LOAD_REGS(kt + KSTEP); }

#pragma unroll
        for (int k8 = 0; k8 < 2; k8++) {
            const int kk = k8 * 8 + (lane & 3);
            unsigned ah[2][4], al[2][4];
#pragma unroll
            for (int i = 0; i < 2; i++) {
                int r = wm * 32 + i * 16 + (lane >> 2);
                uint2 p;
                p = *(const uint2*)&As[r * AS_W + kk * 2];             ah[i][0] = p.x; al[i][0] = p.y;
                p = *(const uint2*)&As[(r + 8) * AS_W + kk * 2];       ah[i][1] = p.x; al[i][1] = p.y;
                p = *(const uint2*)&As[r * AS_W + (kk + 4) * 2];       ah[i][2] = p.x; al[i][2] = p.y;
                p = *(const uint2*)&As[(r + 8) * AS_W + (kk + 4) * 2]; ah[i][3] = p.x; al[i][3] = p.y;
            }
#pragma unroll
            for (int hh = 0; hh < 2; hh++) {
                unsigned bh[4][2], bl[4][2];
#pragma unroll
                for (int j = 0; j < 4; j++) {
                    int c = wn * 64 + hh * 32 + j * 8 + (lane >> 2);
                    uint2 p;
                    p = *(const uint2*)&Bs[kk * BS_W + c * 2];       bh[j][0] = p.x; bl[j][0] = p.y;
                    p = *(const uint2*)&Bs[(kk + 4) * BS_W + c * 2]; bh[j][1] = p.x; bl[j][1] = p.y;
                }
#pragma unroll
                for (int i = 0; i < 2; i++)
#pragma unroll
                    for (int j = 0; j < 4; j++) {
                        float4& c4 = acc[i][hh * 4 + j];
                        mma_tf32(c4, ah[i], bh[j]);
                        mma_tf32(c4, ah[i], bl[j]);
                        mma_tf32(c4, al[i], bh[j]);
                    }
            }
        }
        __syncthreads();
    }

#pragma unroll
    for (int i = 0; i < 2; i++) {
        int r0 = rowBase + wm * 32 + i * 16 + (lane >> 2);
        const float* Ra = nullptr;
        const float* Rb = nullptr;
        if (LIDX >= 0) {
            if (r0 < NN)     Ra = g_R + (size_t)LIDX * NG * HD + (size_t)batch[r0] * HD;
            if (r0 + 8 < NN) Rb = g_R + (size_t)LIDX * NG * HD + (size_t)batch[r0 + 8] * HD;
        }
#pragma unroll
        for (int j = 0; j < 8; j++) {
            int c = colBase + wn * 64 + j * 8 + 2 * (lane & 3);
            float4 v = acc[i][j];
            if (r0 < NN) {
                float2 o = make_float2(v.x, v.y);
                if (LIDX >= 0) { float2 r = *(const float2*)(Ra + c); o.x += r.x; o.y += r.y; }
                *(float2*)(g_h + (size_t)r0 * HD + c) = o;
            }
            if (r0 + 8 < NN) {
                float2 o = make_float2(v.z, v.w);
                if (LIDX >= 0) { float2 r = *(const float2*)(Rb + c); o.x += r.x; o.y += r.y; }
                *(float2*)(g_h + (size_t)(r0 + 8) * HD + c) = o;
            }
        }
    }
#undef LOAD_REGS
}

// ---------------- CSR gather propagation ----------------
template<bool RELU>
__global__ __launch_bounds__(256)
void k_prop(const float* __restrict__ bias) {
    int node = blockIdx.x * 4 + (threadIdx.x >> 6);
    int half = (threadIdx.x >> 5) & 1;
    int lane = threadIdx.x & 31;
    if (node >= NN) return;
    int off = half * 128 + lane * 4;
    float invd = g_inv[node];
    float sq = invd * invd;
    float4 h0 = *(const float4*)(g_h + (size_t)node * HD + off);
    float4 b0 = *(const float4*)(bias + off);
    float4 acc = make_float4(fmaf(h0.x, sq, b0.x), fmaf(h0.y, sq, b0.y),
                             fmaf(h0.z, sq, b0.z), fmaf(h0.w, sq, b0.w));
    int e   = g_rowptr[node];
    int end = g_rowptr[node + 1];
    for (; e + 4 <= end; e += 4) {
        int s0 = g_csrc[e], s1 = g_csrc[e + 1], s2 = g_csrc[e + 2], s3 = g_csrc[e + 3];
        float w0 = g_inv[s0] * invd, w1 = g_inv[s1] * invd;
        float w2 = g_inv[s2] * invd, w3 = g_inv[s3] * invd;
        float4 u0 = *(const float4*)(g_h + (size_t)s0 * HD + off);
        float4 u1 = *(const float4*)(g_h + (size_t)s1 * HD + off);
        float4 u2 = *(const float4*)(g_h + (size_t)s2 * HD + off);
        float4 u3 = *(const float4*)(g_h + (size_t)s3 * HD + off);
        acc.x = fmaf(u0.x, w0, acc.x); acc.y = fmaf(u0.y, w0, acc.y);
        acc.z = fmaf(u0.z, w0, acc.z); acc.w = fmaf(u0.w, w0, acc.w);
        acc.x = fmaf(u1.x, w1, acc.x); acc.y = fmaf(u1.y, w1, acc.y);
        acc.z = fmaf(u1.z, w1, acc.z); acc.w = fmaf(u1.w, w1, acc.w);
        acc.x = fmaf(u2.x, w2, acc.x); acc.y = fmaf(u2.y, w2, acc.y);
        acc.z = fmaf(u2.z, w2, acc.z); acc.w = fmaf(u2.w, w2, acc.w);
        acc.x = fmaf(u3.x, w3, acc.x); acc.y = fmaf(u3.y, w3, acc.y);
        acc.z = fmaf(u3.z, w3, acc.z); acc.w = fmaf(u3.w, w3, acc.w);
    }
    for (; e < end; e++) {
        int s0 = g_csrc[e];
        float w0 = g_inv[s0] * invd;
        float4 u0 = *(const float4*)(g_h + (size_t)s0 * HD + off);
        acc.x = fmaf(u0.x, w0, acc.x); acc.y = fmaf(u0.y, w0, acc.y);
        acc.z = fmaf(u0.z, w0, acc.z); acc.w = fmaf(u0.w, w0, acc.w);
    }
    if (RELU) {
        acc.x = fmaxf(acc.x, 0.f); acc.y = fmaxf(acc.y, 0.f);
        acc.z = fmaxf(acc.z, 0.f); acc.w = fmaxf(acc.w, 0.f);
    }
    *(float4*)(g_z + (size_t)node * HD + off) = acc;
}

// ---------------- pooling + head ----------------
__global__ void k_pool_accum(const int* __restrict__ batch) {
    int w = (blockIdx.x * blockDim.x + threadIdx.x) >> 5;
    int lane = threadIdx.x & 31;
    if (w >= NN) return;
    int b = batch[w];
    const float4* z4 = (const float4*)(g_z + (size_t)w * HD);
    float* gs = g_gmsum + b * HD;
#pragma unroll
    for (int c = lane; c < 64; c += 32) {
        float4 v = z4[c];
        asm volatile("red.global.add.v4.f32 [%0], {%1,%2,%3,%4};"
                     :: "l"(gs + c * 4), "f"(v.x), "f"(v.y), "f"(v.z), "f"(v.w)
                     : "memory");
    }
}
__global__ void k_pool_final(const float* __restrict__ gh, float* __restrict__ out) {
    int t = blockIdx.x * blockDim.x + threadIdx.x;
    if (t >= NG * HD) return;
    int g = t / HD;
    float cnt = (float)max(g_cnt[g], 1);
    float v = g_gmsum[t] / cnt + gh[t];
    g_gm[t] = v;
    out[NG * NC + t] = v;
}
__global__ void k_y(const float* __restrict__ Wlin, const float* __restrict__ blin,
                    float* __restrict__ out) {
    int t = blockIdx.x * blockDim.x + threadIdx.x;
    if (t >= NG * NC) return;
    int g = t / NC, c = t % NC;
    float s = blin[c];
    const float* gm = g_gm + g * HD;
#pragma unroll 8
    for (int k = 0; k < HD; k++) s = fmaf(gm[k], Wlin[k * NC + c], s);
    out[t] = s;
}

// ---------------- launch ----------------
extern "C" void kernel_launch(void* const* d_in, const int* in_sizes, int n_in,
                              void* d_out, int out_size) {
    const float* x     = (const float*)d_in[0];
    const int*   ei    = (const int*)d_in[1];
    const int*   src   = ei;
    const int*   dst   = ei + NE;
    const int*   batch = (const int*)d_in[2];
    const float* gh    = (const float*)d_in[3];
    const float* W0    = (const float*)d_in[4];
    const float* b0    = (const float*)d_in[5];
    const float* Ws    = (const float*)d_in[6];
    const float* bs    = (const float*)d_in[7];
    const float* Wlin  = (const float*)d_in[8];
    const float* blin  = (const float*)d_in[9];
    float* out = (float*)d_out;

    k_init<<<(NN + 255) / 256, 256>>>();
    k_count<<<(NE + 255) / 256, 256>>>(dst, batch);
    const int nsb = (NN + SCAN_B - 1) / SCAN_B;
    k_scan1<<<nsb, SCAN_B>>>();
    k_scan2<<<1, 32>>>(nsb);
    k_scan3<<<nsb, SCAN_B>>>();
    k_scatter<<<(NE + 255) / 256, 256>>>(src, dst);
    k_rgemm<<<dim3(2, NL), 256>>>(gh, Ws);

    dim3 ggrid((NN + 127) / 128, HD / 128);
    const int propBlocks = (NN + 3) / 4;

    k_gemm<FD, -1><<<ggrid, 256>>>(x, W0, nullptr);
    k_prop<false><<<propBlocks, 256>>>(b0);

    k_gemm<HD, 0><<<ggrid, 256>>>(nullptr, Ws + 0 * HD * HD, batch);
    k_prop<true><<<propBlocks, 256>>>(bs + 0 * HD);
    k_gemm<HD, 1><<<ggrid, 256>>>(nullptr, Ws + 1 * (size_t)HD * HD, batch);
    k_prop<true><<<propBlocks, 256>>>(bs + 1 * HD);
    k_gemm<HD, 2><<<ggrid, 256>>>(nullptr, Ws + 2 * (size_t)HD * HD, batch);
    k_prop<true><<<propBlocks, 256>>>(bs + 2 * HD);

    k_pool_accum<<<(int)(((long long)NN * 32 + 255) / 256), 256>>>(batch);
    k_pool_final<<<(NG * HD + 255) / 256, 256>>>(gh, out);
    k_y<<<(NG * NC + 255) / 256, 256>>>(Wlin, blin, out);
}